// round 14
// baseline (speedup 1.0000x reference)
#include <cuda_runtime.h>
#include <cuda_fp16.h>
#include <cstdint>

// Problem constants (fixed by the dataset)
#define B_    8
#define V_    12288
#define E_    98304
#define FIN_  256
#define FOUT_ 256
#define KCH_  4
#define BF_   (B_*FIN_)    // 2048 values per node row
#define ROWS_ (B_*V_)      // 98304 output rows

// ---------------- scratch (device globals: no runtime allocation) ----------
// Self-cleaning invariant: g_cnt, g_sum, g_sq are zero at module load and are
// returned to zero within every kernel_launch call (k_xh re-zeroes g_cnt
// before k_hist; k_bnfinal re-zeroes g_sum/g_sq).
__device__ __half g_Xh[(size_t)B_*V_*FIN_];   // fp16 copy of x
__device__ __half g_T1h[(size_t)V_*BF_];
__device__ __half g_T2h[(size_t)V_*BF_];
__device__ __half g_T3h[(size_t)V_*BF_];
__device__ __half g_Wh[(size_t)KCH_*FIN_*FOUT_];  // fp16 W, k-pair interleaved
__device__ __half g_Oh[(size_t)ROWS_*FOUT_];      // fp16 pre-BN GEMM output
__device__ int   g_rowptr[V_+1];
__device__ int   g_cursor[V_];
__device__ int   g_cnt[V_];
__device__ int   g_col[E_];
__device__ float g_w[E_];
__device__ float g_sum[FOUT_], g_sq[FOUT_];
__device__ float g_scale[FOUT_], g_shift[FOUT_];

__device__ __forceinline__ uint32_t h2u(__half2 h) {
    return *reinterpret_cast<uint32_t*>(&h);
}

// ---------------- x -> fp16 copy (+ zero g_cnt for the CSR hist) ------------
__global__ __launch_bounds__(256) void k_xh(const float* __restrict__ x) {
    long gi = (long)blockIdx.x*256 + threadIdx.x;
    if (gi < V_) g_cnt[gi] = 0;          // runs before k_hist in stream order
    long i = gi * 8;
    float4 a = *(const float4*)(x + i);
    float4 b = *(const float4*)(x + i + 4);
    uint4 o;
    o.x = h2u(__floats2half2_rn(a.x, a.y));
    o.y = h2u(__floats2half2_rn(a.z, a.w));
    o.z = h2u(__floats2half2_rn(b.x, b.y));
    o.w = h2u(__floats2half2_rn(b.z, b.w));
    *(uint4*)(g_Xh + i) = o;
}

// ---------------- w -> fp16, k-pair interleaved (R13-proven) -----------------
__global__ __launch_bounds__(256) void k_wh(const float* __restrict__ w) {
    int p  = blockIdx.x >> 7;            // 4 p-values
    int pk = blockIdx.x & 127;           // 128 k-pairs
    int n  = threadIdx.x;                // 256 columns
    const float* wp = w + (long)p*FIN_*FOUT_;
    float v0 = wp[(long)(2*pk  )*FOUT_ + n];
    float v1 = wp[(long)(2*pk+1)*FOUT_ + n];
    *(uint32_t*)(g_Wh + (((long)p*128 + pk)*FOUT_ + n)*2) =
        h2u(__floats2half2_rn(v0, v1));
}

// ---------------- CSR build (g_cnt zeroed by k_xh) ---------------------------
__global__ void k_hist(const int* __restrict__ dst) {
    int e = blockIdx.x*blockDim.x + threadIdx.x;
    if (e < E_) atomicAdd(&g_cnt[dst[e]], 1);
}

// warp-shuffle scan: 2 barriers instead of 20
__global__ __launch_bounds__(1024) void k_scan() {
    __shared__ int wsum[32];
    int t = threadIdx.x;
    int lane = t & 31, wid = t >> 5;
    int base = t*12;
    int loc[12];
    int s = 0;
    #pragma unroll
    for (int i = 0; i < 12; ++i) { loc[i] = s; s += g_cnt[base+i]; }
    // inclusive scan of s across 1024 threads
    int v = s;
    #pragma unroll
    for (int off = 1; off < 32; off <<= 1) {
        int u = __shfl_up_sync(0xffffffffu, v, off);
        if (lane >= off) v += u;
    }
    if (lane == 31) wsum[wid] = v;
    __syncthreads();
    if (wid == 0) {
        int u = wsum[lane];
        #pragma unroll
        for (int off = 1; off < 32; off <<= 1) {
            int uu = __shfl_up_sync(0xffffffffu, u, off);
            if (lane >= off) u += uu;
        }
        wsum[lane] = u;
    }
    __syncthreads();
    int pre = v - s + (wid ? wsum[wid-1] : 0);   // exclusive prefix for thread
    #pragma unroll
    for (int i = 0; i < 12; ++i) {
        int p = pre + loc[i];
        g_rowptr[base+i] = p;
        g_cursor[base+i] = p;
    }
    if (t == 1023) g_rowptr[V_] = pre + s;
}

__global__ void k_scatter(const int* __restrict__ src, const int* __restrict__ dst,
                          const float* __restrict__ ew) {
    int e = blockIdx.x*blockDim.x + threadIdx.x;
    if (e < E_) {
        int d = dst[e];
        int p = atomicAdd(&g_cursor[d], 1);
        g_col[p] = src[e];
        g_w[p]   = ew[e];
    }
}

// ---------------- SpMM: Chebyshev recursion (fp16 storage, f32 accumulate) --
__global__ __launch_bounds__(256) void k_spmm(int stage) {
    const __half* y;  const __half* p2 = nullptr;  __half* o;
    long ys, ps = 0;
    const int v  = blockIdx.x;
    const int j0 = (blockIdx.y << 10) + threadIdx.x*4;   // 4 halves per thread
    const long xo = (long)(j0>>8)*((long)V_*FIN_) + (j0&255);
    long yo, po = 0;
    if (stage == 1)      { y = g_Xh;  ys = FIN_; yo = xo; o = g_T1h; }
    else if (stage == 2) { y = g_T1h; ys = BF_;  yo = j0;
                           p2 = g_Xh;  ps = FIN_; po = xo; o = g_T2h; }
    else                 { y = g_T2h; ys = BF_;  yo = j0;
                           p2 = g_T1h; ps = BF_;  po = j0; o = g_T3h; }

    int r0 = g_rowptr[v], r1 = g_rowptr[v+1];
    float2 a01 = make_float2(0.f, 0.f), a23 = make_float2(0.f, 0.f);

    int e = r0;
    #pragma unroll 1
    for (; e + 4 <= r1; e += 4) {
        int   s0 = __ldg(&g_col[e]),   s1 = __ldg(&g_col[e+1]);
        int   s2 = __ldg(&g_col[e+2]), s3 = __ldg(&g_col[e+3]);
        float w0 = __ldg(&g_w[e]),     w1 = __ldg(&g_w[e+1]);
        float w2 = __ldg(&g_w[e+2]),   w3 = __ldg(&g_w[e+3]);
        uint2 t0 = *(const uint2*)(y + yo + (long)s0*ys);
        uint2 t1 = *(const uint2*)(y + yo + (long)s1*ys);
        uint2 t2 = *(const uint2*)(y + yo + (long)s2*ys);
        uint2 t3 = *(const uint2*)(y + yo + (long)s3*ys);
        float2 f;
        f = __half22float2(*(__half2*)&t0.x); a01.x = fmaf(w0,f.x,a01.x); a01.y = fmaf(w0,f.y,a01.y);
        f = __half22float2(*(__half2*)&t0.y); a23.x = fmaf(w0,f.x,a23.x); a23.y = fmaf(w0,f.y,a23.y);
        f = __half22float2(*(__half2*)&t1.x); a01.x = fmaf(w1,f.x,a01.x); a01.y = fmaf(w1,f.y,a01.y);
        f = __half22float2(*(__half2*)&t1.y); a23.x = fmaf(w1,f.x,a23.x); a23.y = fmaf(w1,f.y,a23.y);
        f = __half22float2(*(__half2*)&t2.x); a01.x = fmaf(w2,f.x,a01.x); a01.y = fmaf(w2,f.y,a01.y);
        f = __half22float2(*(__half2*)&t2.y); a23.x = fmaf(w2,f.x,a23.x); a23.y = fmaf(w2,f.y,a23.y);
        f = __half22float2(*(__half2*)&t3.x); a01.x = fmaf(w3,f.x,a01.x); a01.y = fmaf(w3,f.y,a01.y);
        f = __half22float2(*(__half2*)&t3.y); a23.x = fmaf(w3,f.x,a23.x); a23.y = fmaf(w3,f.y,a23.y);
    }
    #pragma unroll 1
    for (; e < r1; ++e) {
        int   s0 = __ldg(&g_col[e]);
        float w0 = __ldg(&g_w[e]);
        uint2 t0 = *(const uint2*)(y + yo + (long)s0*ys);
        float2 f;
        f = __half22float2(*(__half2*)&t0.x); a01.x = fmaf(w0,f.x,a01.x); a01.y = fmaf(w0,f.y,a01.y);
        f = __half22float2(*(__half2*)&t0.y); a23.x = fmaf(w0,f.x,a23.x); a23.y = fmaf(w0,f.y,a23.y);
    }
    if (p2) {
        uint2 t0 = *(const uint2*)(p2 + po + (long)v*ps);
        float2 f;
        f = __half22float2(*(__half2*)&t0.x);
        a01.x = 2.f*a01.x - f.x; a01.y = 2.f*a01.y - f.y;
        f = __half22float2(*(__half2*)&t0.y);
        a23.x = 2.f*a23.x - f.x; a23.y = 2.f*a23.y - f.y;
    }
    uint2 r;
    r.x = h2u(__floats2half2_rn(a01.x, a01.y));
    r.y = h2u(__floats2half2_rn(a23.x, a23.y));
    *(uint2*)(o + (long)v*BF_ + j0) = r;
}

// ---------------- FP16 tensor-core GEMM (m16n8k16, fragment-order smem) -----
// out_pre[b,v,o] = sum_p sum_i A_p(v,b,i) * W[p,i,o]  -> g_Oh (fp16)
// A and W both fp16 in memory: both prefetches are raw copies (R13-proven).
// BN stats from f32 accumulators; pre-BN values stored fp16 (halves traffic).
#define BM 64
#define BN 256
#define BK 32
#define NCH (KCH_ * FIN_ / BK)   // 32 chunks

#define ATW 132
#define BTW 66
#define ATILES 8
#define BTILES 64

__global__ __launch_bounds__(256) void k_gemm() {
    __shared__ uint32_t As[2][ATILES*ATW];    //  8448 B
    __shared__ uint32_t Bs[2][BTILES*BTW];    // 33792 B
    __shared__ float s_s[BN], s_q[BN];        //  2048 B

    const int b     = blockIdx.y;
    const int vbase = blockIdx.x * BM;
    const int tid  = threadIdx.x;
    const int lane = tid & 31, warp = tid >> 5;
    const int wm = warp & 1, wn = warp >> 1;   // 2 warps along M, 4 along N

    s_s[tid] = 0.f; s_q[tid] = 0.f;

    float acc[2][8][4];
    #pragma unroll
    for (int i = 0; i < 2; ++i)
        #pragma unroll
        for (int j = 0; j < 8; ++j)
            #pragma unroll
            for (int c = 0; c < 4; ++c) acc[i][j][c] = 0.f;

    uint32_t pa[2][2];      // 2 A items — raw fp16 copy
    uint4    pb[2][2];      // item (pk, ng): n = 8*ng..8*ng+7, 2 uint4

    auto prefetch = [&](int t) {
        const int p  = t >> 3;
        const int kb = (t & 7) * BK;
        const __half* ab; long as_;
        if (p == 0)      { ab = g_Xh  + (long)b*V_*FIN_; as_ = FIN_; }
        else if (p == 1) { ab = g_T1h + (long)b*FIN_;    as_ = BF_;  }
        else if (p == 2) { ab = g_T2h + (long)b*FIN_;    as_ = BF_;  }
        else             { ab = g_T3h + (long)b*FIN_;    as_ = BF_;  }
        #pragma unroll
        for (int i = 0; i < 2; ++i) {
            int item = tid + i*256;            // 0..511
            int row = item >> 3, q = item & 7;
            uint2 v = *(const uint2*)(ab + (long)(vbase+row)*as_ + kb + q*4);
            pa[i][0] = v.x;
            pa[i][1] = v.y;
        }
        const uint32_t* wb = (const uint32_t*)g_Wh + ((long)p*128 + (kb >> 1))*FOUT_;
        #pragma unroll
        for (int i = 0; i < 2; ++i) {
            int item = tid + i*256;
            int pk = item >> 5, ng = item & 31;
            const uint4* src = (const uint4*)(wb + (long)pk*FOUT_ + ng*8);
            pb[i][0] = src[0];
            pb[i][1] = src[1];
        }
    };

    prefetch(0);
    int cur = 0;
    #pragma unroll 1
    for (int t = 0; t < NCH; ++t) {
        uint32_t* Ac = As[cur];
        uint32_t* Bc = Bs[cur];
        #pragma unroll
        for (int i = 0; i < 2; ++i) {
            int item = tid + i*256;
            int row = item >> 3, q = item & 7;
            int tile = (q >> 2)*4 + (row >> 4);
            int ls   = (row & 7)*4 + (q & 1)*2;
            int r4   = ((q >> 1) & 1)*2 + ((row >> 3) & 1);
            uint32_t base = tile*ATW + r4;
            Ac[base + (ls  )*4] = pa[i][0];
            Ac[base + (ls+1)*4] = pa[i][1];
        }
        #pragma unroll
        for (int i = 0; i < 2; ++i) {
            int item = tid + i*256;
            int pk = item >> 5, ng = item & 31;
            int tile = (pk >> 3)*32 + ng;
            uint32_t base = tile*BTW + ((pk >> 2) & 1) + (pk & 3)*2;
            const uint32_t* pv0 = (const uint32_t*)&pb[i][0];
            const uint32_t* pv1 = (const uint32_t*)&pb[i][1];
            #pragma unroll
            for (int j = 0; j < 4; ++j) Bc[base + j*8]     = pv0[j];
            #pragma unroll
            for (int j = 0; j < 4; ++j) Bc[base + (j+4)*8] = pv1[j];
        }
        __syncthreads();
        if (t + 1 < NCH) prefetch(t + 1);   // overlap global loads with mma

        #pragma unroll
        for (int kb2 = 0; kb2 < 2; ++kb2) {   // two k16 steps
            uint32_t a[2][4];
            #pragma unroll
            for (int mt = 0; mt < 2; ++mt) {
                int tile = kb2*4 + wm*2 + mt;
                uint4 av = *(const uint4*)&Ac[tile*ATW + lane*4];
                a[mt][0] = av.x; a[mt][1] = av.y;
                a[mt][2] = av.z; a[mt][3] = av.w;
            }
            #pragma unroll
            for (int nt = 0; nt < 8; ++nt) {
                int tile = kb2*32 + wn*8 + nt;
                uint2 bv = *(const uint2*)&Bc[tile*BTW + lane*2];
                #pragma unroll
                for (int mt = 0; mt < 2; ++mt) {
                    asm volatile(
                        "mma.sync.aligned.m16n8k16.row.col.f32.f16.f16.f32 "
                        "{%0,%1,%2,%3}, {%4,%5,%6,%7}, {%8,%9}, {%0,%1,%2,%3};\n"
                        : "+f"(acc[mt][nt][0]), "+f"(acc[mt][nt][1]),
                          "+f"(acc[mt][nt][2]), "+f"(acc[mt][nt][3])
                        : "r"(a[mt][0]), "r"(a[mt][1]),
                          "r"(a[mt][2]), "r"(a[mt][3]),
                          "r"(bv.x), "r"(bv.y));
                }
            }
        }
        cur ^= 1;
    }

    const int g = lane >> 2, tg = lane & 3;

    // epilogue: write pre-BN result as fp16 (halves write traffic)
    #pragma unroll
    for (int mt = 0; mt < 2; ++mt) {
        int row0 = vbase + wm*32 + mt*16 + g;
        #pragma unroll
        for (int nt = 0; nt < 8; ++nt) {
            int col = wn*64 + nt*8 + tg*2;
            uint32_t v0 = h2u(__floats2half2_rn(acc[mt][nt][0], acc[mt][nt][1]));
            uint32_t v1 = h2u(__floats2half2_rn(acc[mt][nt][2], acc[mt][nt][3]));
            *(uint32_t*)&g_Oh[((long)b*V_ + row0    )*FOUT_ + col] = v0;
            *(uint32_t*)&g_Oh[((long)b*V_ + row0 + 8)*FOUT_ + col] = v1;
        }
    }

    // fused BN stats: per-column sum / sumsq over this block's 64 rows (f32)
    #pragma unroll
    for (int nt = 0; nt < 8; ++nt) {
        float s0 = acc[0][nt][0] + acc[0][nt][2] + acc[1][nt][0] + acc[1][nt][2];
        float s1 = acc[0][nt][1] + acc[0][nt][3] + acc[1][nt][1] + acc[1][nt][3];
        float q0 = acc[0][nt][0]*acc[0][nt][0] + acc[0][nt][2]*acc[0][nt][2]
                 + acc[1][nt][0]*acc[1][nt][0] + acc[1][nt][2]*acc[1][nt][2];
        float q1 = acc[0][nt][1]*acc[0][nt][1] + acc[0][nt][3]*acc[0][nt][3]
                 + acc[1][nt][1]*acc[1][nt][1] + acc[1][nt][3]*acc[1][nt][3];
        #pragma unroll
        for (int m = 4; m <= 16; m <<= 1) {
            s0 += __shfl_xor_sync(0xffffffffu, s0, m);
            s1 += __shfl_xor_sync(0xffffffffu, s1, m);
            q0 += __shfl_xor_sync(0xffffffffu, q0, m);
            q1 += __shfl_xor_sync(0xffffffffu, q1, m);
        }
        if (lane < 4) {
            int colr = wn*64 + nt*8 + tg*2;
            atomicAdd(&s_s[colr  ], s0); atomicAdd(&s_q[colr  ], q0);
            atomicAdd(&s_s[colr+1], s1); atomicAdd(&s_q[colr+1], q1);
        }
    }
    __syncthreads();
    atomicAdd(&g_sum[tid], s_s[tid]);
    atomicAdd(&g_sq[tid],  s_q[tid]);
}

// ---------------- BatchNorm finalize + apply + ReLU -------------------------
__global__ void k_bnfinal(const float* __restrict__ gamma,
                          const float* __restrict__ beta) {
    int o = threadIdx.x;
    const float n = (float)ROWS_;
    float mean = g_sum[o] / n;
    float var  = g_sq[o] / n - mean*mean;      // biased variance (torch-style)
    float sc   = gamma[o] * rsqrtf(var + 1e-5f);
    g_scale[o] = sc;
    g_shift[o] = beta[o] - mean*sc;
    g_sum[o] = 0.f;                 // self-clean for next call
    g_sq[o]  = 0.f;
}

__global__ __launch_bounds__(256) void k_bnapply(float* __restrict__ out) {
    long i = ((long)blockIdx.x*blockDim.x + threadIdx.x) * 4;
    uint2 h = *(const uint2*)(g_Oh + i);
    float2 f0 = __half22float2(*(__half2*)&h.x);
    float2 f1 = __half22float2(*(__half2*)&h.y);
    int o = (int)(i & 255);
    float4 v;
    v.x = fmaxf(fmaf(f0.x, g_scale[o  ], g_shift[o  ]), 0.f);
    v.y = fmaxf(fmaf(f0.y, g_scale[o+1], g_shift[o+1]), 0.f);
    v.z = fmaxf(fmaf(f1.x, g_scale[o+2], g_shift[o+2]), 0.f);
    v.w = fmaxf(fmaf(f1.y, g_scale[o+3], g_shift[o+3]), 0.f);
    *(float4*)(out + i) = v;
}

// ---------------- launch -----------------------------------------------------
extern "C" void kernel_launch(void* const* d_in, const int* in_sizes, int n_in,
                              void* d_out, int out_size) {
    const float* x     = (const float*)d_in[0];
    const float* ew    = (const float*)d_in[1];
    const float* w     = (const float*)d_in[2];
    const float* bias  = (const float*)d_in[3]; (void)bias; // cancels under BN
    const float* gamma = (const float*)d_in[4];
    const float* beta  = (const float*)d_in[5];
    const int*   esrc  = (const int*)d_in[6];
    const int*   edst  = (const int*)d_in[7];
    float* out = (float*)d_out;
    (void)in_sizes; (void)n_in; (void)out_size;

    // fp16 conversions (k_xh also zeroes g_cnt ahead of k_hist)
    k_xh<<<(B_*V_*FIN_)/(256*8), 256>>>(x);
    k_wh<<<KCH_*128, 256>>>(w);

    // CSR build
    k_hist<<<E_/256, 256>>>(edst);
    k_scan<<<1, 1024>>>();
    k_scatter<<<E_/256, 256>>>(esrc, edst, ew);

    // Chebyshev recursion (fp16 storage, f32 accumulate; batch-halved grid)
    dim3 gs(V_, 2);
    k_spmm<<<gs, 256>>>(1);
    k_spmm<<<gs, 256>>>(2);
    k_spmm<<<gs, 256>>>(3);

    // FP16 tensor-core GEMM -> fp16 pre-BN output + fused BN statistics
    dim3 gg(V_/BM, B_);
    k_gemm<<<gg, 256>>>();

    // BatchNorm finalize + apply + ReLU (fp16 in, f32 out)
    k_bnfinal<<<1, FOUT_>>>(gamma, beta);
    k_bnapply<<<(ROWS_*FOUT_)/4/256, 256>>>(out);
}

// round 15
// speedup vs baseline: 1.0946x; 1.0946x over previous
#include <cuda_runtime.h>
#include <cuda_fp16.h>
#include <cstdint>

// Problem constants (fixed by the dataset)
#define B_    8
#define V_    12288
#define E_    98304
#define FIN_  256
#define FOUT_ 256
#define KCH_  4
#define BF_   (B_*FIN_)    // 2048 values per node row
#define ROWS_ (B_*V_)      // 98304 output rows

// ---------------- scratch (device globals: no runtime allocation) ----------
// Self-cleaning invariant: g_cnt, g_sum, g_sq are zero at module load and are
// returned to zero within every kernel_launch call.
__device__ __half g_Xh[(size_t)B_*V_*FIN_];   // fp16 copy of x
__device__ __half g_T1h[(size_t)V_*BF_];
__device__ __half g_T2h[(size_t)V_*BF_];
__device__ __half g_T3h[(size_t)V_*BF_];
__device__ __half g_Wh[(size_t)KCH_*FIN_*FOUT_];  // fp16 W, k-pair interleaved
__device__ __half g_Oh[(size_t)ROWS_*FOUT_];      // fp16 pre-BN GEMM output
__device__ int   g_rowptr[V_+1];
__device__ int   g_cursor[V_];
__device__ int   g_cnt[V_];
__device__ int   g_col[E_];
__device__ float g_w[E_];
__device__ float g_sum[FOUT_], g_sq[FOUT_];
__device__ float g_scale[FOUT_], g_shift[FOUT_];

__device__ __forceinline__ uint32_t h2u(__half2 h) {
    return *reinterpret_cast<uint32_t*>(&h);
}

// ---------------- x -> fp16 copy (+ zero g_cnt for the CSR hist) ------------
__global__ __launch_bounds__(256) void k_xh(const float* __restrict__ x) {
    long gi = (long)blockIdx.x*256 + threadIdx.x;
    if (gi < V_) g_cnt[gi] = 0;          // runs before k_hist in stream order
    long i = gi * 8;
    float4 a = *(const float4*)(x + i);
    float4 b = *(const float4*)(x + i + 4);
    uint4 o;
    o.x = h2u(__floats2half2_rn(a.x, a.y));
    o.y = h2u(__floats2half2_rn(a.z, a.w));
    o.z = h2u(__floats2half2_rn(b.x, b.y));
    o.w = h2u(__floats2half2_rn(b.z, b.w));
    *(uint4*)(g_Xh + i) = o;
}

// ---------------- w -> fp16, k-pair interleaved (R13-proven) -----------------
__global__ __launch_bounds__(256) void k_wh(const float* __restrict__ w) {
    int p  = blockIdx.x >> 7;            // 4 p-values
    int pk = blockIdx.x & 127;           // 128 k-pairs
    int n  = threadIdx.x;                // 256 columns
    const float* wp = w + (long)p*FIN_*FOUT_;
    float v0 = wp[(long)(2*pk  )*FOUT_ + n];
    float v1 = wp[(long)(2*pk+1)*FOUT_ + n];
    *(uint32_t*)(g_Wh + (((long)p*128 + pk)*FOUT_ + n)*2) =
        h2u(__floats2half2_rn(v0, v1));
}

// ---------------- CSR build (g_cnt zeroed by k_xh) ---------------------------
__global__ void k_hist(const int* __restrict__ dst) {
    int e = blockIdx.x*blockDim.x + threadIdx.x;
    if (e < E_) atomicAdd(&g_cnt[dst[e]], 1);
}

// warp-shuffle scan + int4-vectorized loads/stores
__global__ __launch_bounds__(1024) void k_scan() {
    __shared__ int wsum[32];
    int t = threadIdx.x;
    int lane = t & 31, wid = t >> 5;
    int base = t*12;                      // 12t % 4 == 0 -> int4-aligned
    int c[12];
    {
        const int4* cp = (const int4*)(g_cnt + base);
        int4 a = cp[0], bq = cp[1], d = cp[2];
        c[0]=a.x; c[1]=a.y; c[2]=a.z; c[3]=a.w;
        c[4]=bq.x; c[5]=bq.y; c[6]=bq.z; c[7]=bq.w;
        c[8]=d.x; c[9]=d.y; c[10]=d.z; c[11]=d.w;
    }
    int loc[12];
    int s = 0;
    #pragma unroll
    for (int i = 0; i < 12; ++i) { loc[i] = s; s += c[i]; }
    int v = s;
    #pragma unroll
    for (int off = 1; off < 32; off <<= 1) {
        int u = __shfl_up_sync(0xffffffffu, v, off);
        if (lane >= off) v += u;
    }
    if (lane == 31) wsum[wid] = v;
    __syncthreads();
    if (wid == 0) {
        int u = wsum[lane];
        #pragma unroll
        for (int off = 1; off < 32; off <<= 1) {
            int uu = __shfl_up_sync(0xffffffffu, u, off);
            if (lane >= off) u += uu;
        }
        wsum[lane] = u;
    }
    __syncthreads();
    int pre = v - s + (wid ? wsum[wid-1] : 0);
    int p[12];
    #pragma unroll
    for (int i = 0; i < 12; ++i) p[i] = pre + loc[i];
    {
        int4* rp = (int4*)(g_rowptr + base);
        int4* cu = (int4*)(g_cursor + base);
        int4 a = make_int4(p[0],p[1],p[2],p[3]);
        int4 bq = make_int4(p[4],p[5],p[6],p[7]);
        int4 d = make_int4(p[8],p[9],p[10],p[11]);
        rp[0]=a; rp[1]=bq; rp[2]=d;
        cu[0]=a; cu[1]=bq; cu[2]=d;
    }
    if (t == 1023) g_rowptr[V_] = pre + s;
}

__global__ void k_scatter(const int* __restrict__ src, const int* __restrict__ dst,
                          const float* __restrict__ ew) {
    int e = blockIdx.x*blockDim.x + threadIdx.x;
    if (e < E_) {
        int d = dst[e];
        int p = atomicAdd(&g_cursor[d], 1);
        g_col[p] = src[e];
        g_w[p]   = ew[e];
    }
}

// ---------------- SpMM: Chebyshev recursion (fp16, uint4 gathers) -----------
// one block per node; 256 threads x 8 halves (one uint4 gather per edge).
// fp16 working set = 50MB < L2, so no batch split needed.
__device__ __forceinline__ void acc8(float* a, float wt, uint4 t) {
    float2 f;
    f = __half22float2(*(__half2*)&t.x); a[0] = fmaf(wt,f.x,a[0]); a[1] = fmaf(wt,f.y,a[1]);
    f = __half22float2(*(__half2*)&t.y); a[2] = fmaf(wt,f.x,a[2]); a[3] = fmaf(wt,f.y,a[3]);
    f = __half22float2(*(__half2*)&t.z); a[4] = fmaf(wt,f.x,a[4]); a[5] = fmaf(wt,f.y,a[5]);
    f = __half22float2(*(__half2*)&t.w); a[6] = fmaf(wt,f.x,a[6]); a[7] = fmaf(wt,f.y,a[7]);
}

__global__ __launch_bounds__(256) void k_spmm(int stage) {
    const __half* y;  const __half* p2 = nullptr;  __half* o;
    long ys, ps = 0;
    const int v  = blockIdx.x;
    const int j0 = threadIdx.x*8;                        // 0..2047
    const long xo = (long)(j0>>8)*((long)V_*FIN_) + (j0&255);
    long yo, po = 0;
    if (stage == 1)      { y = g_Xh;  ys = FIN_; yo = xo; o = g_T1h; }
    else if (stage == 2) { y = g_T1h; ys = BF_;  yo = j0;
                           p2 = g_Xh;  ps = FIN_; po = xo; o = g_T2h; }
    else                 { y = g_T2h; ys = BF_;  yo = j0;
                           p2 = g_T1h; ps = BF_;  po = j0; o = g_T3h; }

    int r0 = g_rowptr[v], r1 = g_rowptr[v+1];
    float a[8] = {0.f,0.f,0.f,0.f,0.f,0.f,0.f,0.f};

    int e = r0;
    #pragma unroll 1
    for (; e + 4 <= r1; e += 4) {
        int   s0 = __ldg(&g_col[e]),   s1 = __ldg(&g_col[e+1]);
        int   s2 = __ldg(&g_col[e+2]), s3 = __ldg(&g_col[e+3]);
        float w0 = __ldg(&g_w[e]),     w1 = __ldg(&g_w[e+1]);
        float w2 = __ldg(&g_w[e+2]),   w3 = __ldg(&g_w[e+3]);
        uint4 t0 = *(const uint4*)(y + yo + (long)s0*ys);
        uint4 t1 = *(const uint4*)(y + yo + (long)s1*ys);
        uint4 t2 = *(const uint4*)(y + yo + (long)s2*ys);
        uint4 t3 = *(const uint4*)(y + yo + (long)s3*ys);
        acc8(a, w0, t0);
        acc8(a, w1, t1);
        acc8(a, w2, t2);
        acc8(a, w3, t3);
    }
    #pragma unroll 1
    for (; e < r1; ++e) {
        int   s0 = __ldg(&g_col[e]);
        float w0 = __ldg(&g_w[e]);
        uint4 t0 = *(const uint4*)(y + yo + (long)s0*ys);
        acc8(a, w0, t0);
    }
    if (p2) {
        uint4 t0 = *(const uint4*)(p2 + po + (long)v*ps);
        float2 f;
        f = __half22float2(*(__half2*)&t0.x); a[0] = 2.f*a[0]-f.x; a[1] = 2.f*a[1]-f.y;
        f = __half22float2(*(__half2*)&t0.y); a[2] = 2.f*a[2]-f.x; a[3] = 2.f*a[3]-f.y;
        f = __half22float2(*(__half2*)&t0.z); a[4] = 2.f*a[4]-f.x; a[5] = 2.f*a[5]-f.y;
        f = __half22float2(*(__half2*)&t0.w); a[6] = 2.f*a[6]-f.x; a[7] = 2.f*a[7]-f.y;
    }
    uint4 r;
    r.x = h2u(__floats2half2_rn(a[0], a[1]));
    r.y = h2u(__floats2half2_rn(a[2], a[3]));
    r.z = h2u(__floats2half2_rn(a[4], a[5]));
    r.w = h2u(__floats2half2_rn(a[6], a[7]));
    *(uint4*)(o + (long)v*BF_ + j0) = r;
}

// ---------------- FP16 tensor-core GEMM (m16n8k16, fragment-order smem) -----
// (R13/R14-proven; unchanged this round)
#define BM 64
#define BN 256
#define BK 32
#define NCH (KCH_ * FIN_ / BK)   // 32 chunks

#define ATW 132
#define BTW 66
#define ATILES 8
#define BTILES 64

__global__ __launch_bounds__(256) void k_gemm() {
    __shared__ uint32_t As[2][ATILES*ATW];    //  8448 B
    __shared__ uint32_t Bs[2][BTILES*BTW];    // 33792 B
    __shared__ float s_s[BN], s_q[BN];        //  2048 B

    const int b     = blockIdx.y;
    const int vbase = blockIdx.x * BM;
    const int tid  = threadIdx.x;
    const int lane = tid & 31, warp = tid >> 5;
    const int wm = warp & 1, wn = warp >> 1;   // 2 warps along M, 4 along N

    s_s[tid] = 0.f; s_q[tid] = 0.f;

    float acc[2][8][4];
    #pragma unroll
    for (int i = 0; i < 2; ++i)
        #pragma unroll
        for (int j = 0; j < 8; ++j)
            #pragma unroll
            for (int c = 0; c < 4; ++c) acc[i][j][c] = 0.f;

    uint32_t pa[2][2];
    uint4    pb[2][2];

    auto prefetch = [&](int t) {
        const int p  = t >> 3;
        const int kb = (t & 7) * BK;
        const __half* ab; long as_;
        if (p == 0)      { ab = g_Xh  + (long)b*V_*FIN_; as_ = FIN_; }
        else if (p == 1) { ab = g_T1h + (long)b*FIN_;    as_ = BF_;  }
        else if (p == 2) { ab = g_T2h + (long)b*FIN_;    as_ = BF_;  }
        else             { ab = g_T3h + (long)b*FIN_;    as_ = BF_;  }
        #pragma unroll
        for (int i = 0; i < 2; ++i) {
            int item = tid + i*256;
            int row = item >> 3, q = item & 7;
            uint2 v = *(const uint2*)(ab + (long)(vbase+row)*as_ + kb + q*4);
            pa[i][0] = v.x;
            pa[i][1] = v.y;
        }
        const uint32_t* wb = (const uint32_t*)g_Wh + ((long)p*128 + (kb >> 1))*FOUT_;
        #pragma unroll
        for (int i = 0; i < 2; ++i) {
            int item = tid + i*256;
            int pk = item >> 5, ng = item & 31;
            const uint4* src = (const uint4*)(wb + (long)pk*FOUT_ + ng*8);
            pb[i][0] = src[0];
            pb[i][1] = src[1];
        }
    };

    prefetch(0);
    int cur = 0;
    #pragma unroll 1
    for (int t = 0; t < NCH; ++t) {
        uint32_t* Ac = As[cur];
        uint32_t* Bc = Bs[cur];
        #pragma unroll
        for (int i = 0; i < 2; ++i) {
            int item = tid + i*256;
            int row = item >> 3, q = item & 7;
            int tile = (q >> 2)*4 + (row >> 4);
            int ls   = (row & 7)*4 + (q & 1)*2;
            int r4   = ((q >> 1) & 1)*2 + ((row >> 3) & 1);
            uint32_t base = tile*ATW + r4;
            Ac[base + (ls  )*4] = pa[i][0];
            Ac[base + (ls+1)*4] = pa[i][1];
        }
        #pragma unroll
        for (int i = 0; i < 2; ++i) {
            int item = tid + i*256;
            int pk = item >> 5, ng = item & 31;
            int tile = (pk >> 3)*32 + ng;
            uint32_t base = tile*BTW + ((pk >> 2) & 1) + (pk & 3)*2;
            const uint32_t* pv0 = (const uint32_t*)&pb[i][0];
            const uint32_t* pv1 = (const uint32_t*)&pb[i][1];
            #pragma unroll
            for (int j = 0; j < 4; ++j) Bc[base + j*8]     = pv0[j];
            #pragma unroll
            for (int j = 0; j < 4; ++j) Bc[base + (j+4)*8] = pv1[j];
        }
        __syncthreads();
        if (t + 1 < NCH) prefetch(t + 1);

        #pragma unroll
        for (int kb2 = 0; kb2 < 2; ++kb2) {
            uint32_t a[2][4];
            #pragma unroll
            for (int mt = 0; mt < 2; ++mt) {
                int tile = kb2*4 + wm*2 + mt;
                uint4 av = *(const uint4*)&Ac[tile*ATW + lane*4];
                a[mt][0] = av.x; a[mt][1] = av.y;
                a[mt][2] = av.z; a[mt][3] = av.w;
            }
            #pragma unroll
            for (int nt = 0; nt < 8; ++nt) {
                int tile = kb2*32 + wn*8 + nt;
                uint2 bv = *(const uint2*)&Bc[tile*BTW + lane*2];
                #pragma unroll
                for (int mt = 0; mt < 2; ++mt) {
                    asm volatile(
                        "mma.sync.aligned.m16n8k16.row.col.f32.f16.f16.f32 "
                        "{%0,%1,%2,%3}, {%4,%5,%6,%7}, {%8,%9}, {%0,%1,%2,%3};\n"
                        : "+f"(acc[mt][nt][0]), "+f"(acc[mt][nt][1]),
                          "+f"(acc[mt][nt][2]), "+f"(acc[mt][nt][3])
                        : "r"(a[mt][0]), "r"(a[mt][1]),
                          "r"(a[mt][2]), "r"(a[mt][3]),
                          "r"(bv.x), "r"(bv.y));
                }
            }
        }
        cur ^= 1;
    }

    const int g = lane >> 2, tg = lane & 3;

    // epilogue: write pre-BN result as fp16
    #pragma unroll
    for (int mt = 0; mt < 2; ++mt) {
        int row0 = vbase + wm*32 + mt*16 + g;
        #pragma unroll
        for (int nt = 0; nt < 8; ++nt) {
            int col = wn*64 + nt*8 + tg*2;
            uint32_t v0 = h2u(__floats2half2_rn(acc[mt][nt][0], acc[mt][nt][1]));
            uint32_t v1 = h2u(__floats2half2_rn(acc[mt][nt][2], acc[mt][nt][3]));
            *(uint32_t*)&g_Oh[((long)b*V_ + row0    )*FOUT_ + col] = v0;
            *(uint32_t*)&g_Oh[((long)b*V_ + row0 + 8)*FOUT_ + col] = v1;
        }
    }

    // fused BN stats: per-column sum / sumsq over this block's 64 rows (f32)
    #pragma unroll
    for (int nt = 0; nt < 8; ++nt) {
        float s0 = acc[0][nt][0] + acc[0][nt][2] + acc[1][nt][0] + acc[1][nt][2];
        float s1 = acc[0][nt][1] + acc[0][nt][3] + acc[1][nt][1] + acc[1][nt][3];
        float q0 = acc[0][nt][0]*acc[0][nt][0] + acc[0][nt][2]*acc[0][nt][2]
                 + acc[1][nt][0]*acc[1][nt][0] + acc[1][nt][2]*acc[1][nt][2];
        float q1 = acc[0][nt][1]*acc[0][nt][1] + acc[0][nt][3]*acc[0][nt][3]
                 + acc[1][nt][1]*acc[1][nt][1] + acc[1][nt][3]*acc[1][nt][3];
        #pragma unroll
        for (int m = 4; m <= 16; m <<= 1) {
            s0 += __shfl_xor_sync(0xffffffffu, s0, m);
            s1 += __shfl_xor_sync(0xffffffffu, s1, m);
            q0 += __shfl_xor_sync(0xffffffffu, q0, m);
            q1 += __shfl_xor_sync(0xffffffffu, q1, m);
        }
        if (lane < 4) {
            int colr = wn*64 + nt*8 + tg*2;
            atomicAdd(&s_s[colr  ], s0); atomicAdd(&s_q[colr  ], q0);
            atomicAdd(&s_s[colr+1], s1); atomicAdd(&s_q[colr+1], q1);
        }
    }
    __syncthreads();
    atomicAdd(&g_sum[tid], s_s[tid]);
    atomicAdd(&g_sq[tid],  s_q[tid]);
}

// ---------------- BatchNorm finalize + apply + ReLU -------------------------
__global__ void k_bnfinal(const float* __restrict__ gamma,
                          const float* __restrict__ beta) {
    int o = threadIdx.x;
    const float n = (float)ROWS_;
    float mean = g_sum[o] / n;
    float var  = g_sq[o] / n - mean*mean;      // biased variance (torch-style)
    float sc   = gamma[o] * rsqrtf(var + 1e-5f);
    g_scale[o] = sc;
    g_shift[o] = beta[o] - mean*sc;
    g_sum[o] = 0.f;
    g_sq[o]  = 0.f;
}

__global__ __launch_bounds__(256) void k_bnapply(float* __restrict__ out) {
    long i = ((long)blockIdx.x*blockDim.x + threadIdx.x) * 8;
    uint4 h = *(const uint4*)(g_Oh + i);
    float2 f0 = __half22float2(*(__half2*)&h.x);
    float2 f1 = __half22float2(*(__half2*)&h.y);
    float2 f2 = __half22float2(*(__half2*)&h.z);
    float2 f3 = __half22float2(*(__half2*)&h.w);
    int o = (int)(i & 255);
    float4 v0, v1;
    v0.x = fmaxf(fmaf(f0.x, g_scale[o  ], g_shift[o  ]), 0.f);
    v0.y = fmaxf(fmaf(f0.y, g_scale[o+1], g_shift[o+1]), 0.f);
    v0.z = fmaxf(fmaf(f1.x, g_scale[o+2], g_shift[o+2]), 0.f);
    v0.w = fmaxf(fmaf(f1.y, g_scale[o+3], g_shift[o+3]), 0.f);
    v1.x = fmaxf(fmaf(f2.x, g_scale[o+4], g_shift[o+4]), 0.f);
    v1.y = fmaxf(fmaf(f2.y, g_scale[o+5], g_shift[o+5]), 0.f);
    v1.z = fmaxf(fmaf(f3.x, g_scale[o+6], g_shift[o+6]), 0.f);
    v1.w = fmaxf(fmaf(f3.y, g_scale[o+7], g_shift[o+7]), 0.f);
    *(float4*)(out + i)     = v0;
    *(float4*)(out + i + 4) = v1;
}

// ---------------- launch -----------------------------------------------------
extern "C" void kernel_launch(void* const* d_in, const int* in_sizes, int n_in,
                              void* d_out, int out_size) {
    const float* x     = (const float*)d_in[0];
    const float* ew    = (const float*)d_in[1];
    const float* w     = (const float*)d_in[2];
    const float* bias  = (const float*)d_in[3]; (void)bias; // cancels under BN
    const float* gamma = (const float*)d_in[4];
    const float* beta  = (const float*)d_in[5];
    const int*   esrc  = (const int*)d_in[6];
    const int*   edst  = (const int*)d_in[7];
    float* out = (float*)d_out;
    (void)in_sizes; (void)n_in; (void)out_size;

    // fp16 conversions (k_xh also zeroes g_cnt ahead of k_hist)
    k_xh<<<(B_*V_*FIN_)/(256*8), 256>>>(x);
    k_wh<<<KCH_*128, 256>>>(w);

    // CSR build
    k_hist<<<E_/256, 256>>>(edst);
    k_scan<<<1, 1024>>>();
    k_scatter<<<E_/256, 256>>>(esrc, edst, ew);

    // Chebyshev recursion (fp16, full-row blocks, uint4 gathers)
    k_spmm<<<V_, 256>>>(1);
    k_spmm<<<V_, 256>>>(2);
    k_spmm<<<V_, 256>>>(3);

    // FP16 tensor-core GEMM -> fp16 pre-BN output + fused BN statistics
    dim3 gg(V_/BM, B_);
    k_gemm<<<gg, 256>>>();

    // BatchNorm finalize + apply + ReLU (fp16 in, f32 out)
    k_bnfinal<<<1, FOUT_>>>(gamma, beta);
    k_bnapply<<<(ROWS_*FOUT_)/8/256, 256>>>(out);
}

// round 17
// speedup vs baseline: 1.2560x; 1.1474x over previous
#include <cuda_runtime.h>
#include <cuda_fp16.h>
#include <cstdint>

// Problem constants (fixed by the dataset)
#define B_    8
#define V_    12288
#define E_    98304
#define FIN_  256
#define FOUT_ 256
#define KCH_  4
#define BF_   (B_*FIN_)    // 2048 values per node row
#define ROWS_ (B_*V_)      // 98304 output rows

// ---------------- scratch (device globals: no runtime allocation) ----------
__device__ __half g_Xh[(size_t)B_*V_*FIN_];   // fp16 copy of x
__device__ __half g_T1h[(size_t)V_*BF_];
__device__ __half g_T2h[(size_t)V_*BF_];
__device__ __half g_T3h[(size_t)V_*BF_];
__device__ __half g_Wh[(size_t)KCH_*FIN_*FOUT_];  // fp16 W, plain [p][k][n]
__device__ __half g_Oh[(size_t)ROWS_*FOUT_];      // fp16 pre-BN GEMM output
__device__ int   g_rowptr[V_+1];
__device__ int   g_cursor[V_];
__device__ int   g_cnt[V_];
__device__ int2  g_cw[E_];               // packed (src col, weight bits)
__device__ float g_sum[FOUT_], g_sq[FOUT_];
__device__ float g_scale[FOUT_], g_shift[FOUT_];

__device__ __forceinline__ uint32_t h2u(__half2 h) {
    return *reinterpret_cast<uint32_t*>(&h);
}

// ---------------- x -> fp16 copy (+ zero g_cnt for the CSR hist) ------------
__global__ __launch_bounds__(256) void k_xh(const float* __restrict__ x) {
    long gi = (long)blockIdx.x*256 + threadIdx.x;
    if (gi < V_) g_cnt[gi] = 0;          // runs before k_hist in stream order
    long i = gi * 8;
    float4 a = *(const float4*)(x + i);
    float4 b = *(const float4*)(x + i + 4);
    uint4 o;
    o.x = h2u(__floats2half2_rn(a.x, a.y));
    o.y = h2u(__floats2half2_rn(a.z, a.w));
    o.z = h2u(__floats2half2_rn(b.x, b.y));
    o.w = h2u(__floats2half2_rn(b.z, b.w));
    *(uint4*)(g_Xh + i) = o;
}

// ---------------- w -> fp16, plain [p][k][n] ---------------------------------
__global__ __launch_bounds__(128) void k_wh(const float* __restrict__ w) {
    int p = blockIdx.x >> 8;             // 4 p-values
    int k = blockIdx.x & 255;            // 256 k-rows
    int n2 = threadIdx.x;                // 128 n-pairs
    const float* wp = w + ((long)p*FIN_ + k)*FOUT_;
    float2 v = *(const float2*)(wp + n2*2);
    *(uint32_t*)(g_Wh + ((long)p*FIN_ + k)*FOUT_ + n2*2) =
        h2u(__floats2half2_rn(v.x, v.y));
}

// ---------------- CSR build (g_cnt zeroed by k_xh) ---------------------------
__global__ void k_hist(const int* __restrict__ dst) {
    int e = blockIdx.x*blockDim.x + threadIdx.x;
    if (e < E_) atomicAdd(&g_cnt[dst[e]], 1);
}

// warp-shuffle scan + int4-vectorized loads/stores (R15-proven)
__global__ __launch_bounds__(1024) void k_scan() {
    __shared__ int wsum[32];
    int t = threadIdx.x;
    int lane = t & 31, wid = t >> 5;
    int base = t*12;
    int c[12];
    {
        const int4* cp = (const int4*)(g_cnt + base);
        int4 a = cp[0], bq = cp[1], d = cp[2];
        c[0]=a.x; c[1]=a.y; c[2]=a.z; c[3]=a.w;
        c[4]=bq.x; c[5]=bq.y; c[6]=bq.z; c[7]=bq.w;
        c[8]=d.x; c[9]=d.y; c[10]=d.z; c[11]=d.w;
    }
    int loc[12];
    int s = 0;
    #pragma unroll
    for (int i = 0; i < 12; ++i) { loc[i] = s; s += c[i]; }
    int v = s;
    #pragma unroll
    for (int off = 1; off < 32; off <<= 1) {
        int u = __shfl_up_sync(0xffffffffu, v, off);
        if (lane >= off) v += u;
    }
    if (lane == 31) wsum[wid] = v;
    __syncthreads();
    if (wid == 0) {
        int u = wsum[lane];
        #pragma unroll
        for (int off = 1; off < 32; off <<= 1) {
            int uu = __shfl_up_sync(0xffffffffu, u, off);
            if (lane >= off) u += uu;
        }
        wsum[lane] = u;
    }
    __syncthreads();
    int pre = v - s + (wid ? wsum[wid-1] : 0);
    int p[12];
    #pragma unroll
    for (int i = 0; i < 12; ++i) p[i] = pre + loc[i];
    {
        int4* rp = (int4*)(g_rowptr + base);
        int4* cu = (int4*)(g_cursor + base);
        int4 a = make_int4(p[0],p[1],p[2],p[3]);
        int4 bq = make_int4(p[4],p[5],p[6],p[7]);
        int4 d = make_int4(p[8],p[9],p[10],p[11]);
        rp[0]=a; rp[1]=bq; rp[2]=d;
        cu[0]=a; cu[1]=bq; cu[2]=d;
    }
    if (t == 1023) g_rowptr[V_] = pre + s;
}

__global__ void k_scatter(const int* __restrict__ src, const int* __restrict__ dst,
                          const float* __restrict__ ew) {
    int e = blockIdx.x*blockDim.x + threadIdx.x;
    if (e < E_) {
        int d = dst[e];
        int p = atomicAdd(&g_cursor[d], 1);
        g_cw[p] = make_int2(src[e], __float_as_int(ew[e]));
    }
}

// ---------------- SpMM: Chebyshev recursion (fp16, uint4 gathers) -----------
__device__ __forceinline__ void acc8(float* a, float wt, uint4 t) {
    float2 f;
    f = __half22float2(*(__half2*)&t.x); a[0] = fmaf(wt,f.x,a[0]); a[1] = fmaf(wt,f.y,a[1]);
    f = __half22float2(*(__half2*)&t.y); a[2] = fmaf(wt,f.x,a[2]); a[3] = fmaf(wt,f.y,a[3]);
    f = __half22float2(*(__half2*)&t.z); a[4] = fmaf(wt,f.x,a[4]); a[5] = fmaf(wt,f.y,a[5]);
    f = __half22float2(*(__half2*)&t.w); a[6] = fmaf(wt,f.x,a[6]); a[7] = fmaf(wt,f.y,a[7]);
}

__global__ __launch_bounds__(256) void k_spmm(int stage) {
    const __half* y;  const __half* p2 = nullptr;  __half* o;
    long ys, ps = 0;
    const int v  = blockIdx.x;
    const int j0 = threadIdx.x*8;                        // 0..2047
    const long xo = (long)(j0>>8)*((long)V_*FIN_) + (j0&255);
    long yo, po = 0;
    if (stage == 1)      { y = g_Xh;  ys = FIN_; yo = xo; o = g_T1h; }
    else if (stage == 2) { y = g_T1h; ys = BF_;  yo = j0;
                           p2 = g_Xh;  ps = FIN_; po = xo; o = g_T2h; }
    else                 { y = g_T2h; ys = BF_;  yo = j0;
                           p2 = g_T1h; ps = BF_;  po = j0; o = g_T3h; }

    int r0 = g_rowptr[v], r1 = g_rowptr[v+1];
    float a[8] = {0.f,0.f,0.f,0.f,0.f,0.f,0.f,0.f};

    int e = r0;
    #pragma unroll 1
    for (; e + 4 <= r1; e += 4) {
        int2 c0 = __ldg(&g_cw[e]),   c1 = __ldg(&g_cw[e+1]);
        int2 c2 = __ldg(&g_cw[e+2]), c3 = __ldg(&g_cw[e+3]);
        uint4 t0 = *(const uint4*)(y + yo + (long)c0.x*ys);
        uint4 t1 = *(const uint4*)(y + yo + (long)c1.x*ys);
        uint4 t2 = *(const uint4*)(y + yo + (long)c2.x*ys);
        uint4 t3 = *(const uint4*)(y + yo + (long)c3.x*ys);
        acc8(a, __int_as_float(c0.y), t0);
        acc8(a, __int_as_float(c1.y), t1);
        acc8(a, __int_as_float(c2.y), t2);
        acc8(a, __int_as_float(c3.y), t3);
    }
    #pragma unroll 1
    for (; e < r1; ++e) {
        int2 c0 = __ldg(&g_cw[e]);
        uint4 t0 = *(const uint4*)(y + yo + (long)c0.x*ys);
        acc8(a, __int_as_float(c0.y), t0);
    }
    if (p2) {
        uint4 t0 = *(const uint4*)(p2 + po + (long)v*ps);
        float2 f;
        f = __half22float2(*(__half2*)&t0.x); a[0] = 2.f*a[0]-f.x; a[1] = 2.f*a[1]-f.y;
        f = __half22float2(*(__half2*)&t0.y); a[2] = 2.f*a[2]-f.x; a[3] = 2.f*a[3]-f.y;
        f = __half22float2(*(__half2*)&t0.z); a[4] = 2.f*a[4]-f.x; a[5] = 2.f*a[5]-f.y;
        f = __half22float2(*(__half2*)&t0.w); a[6] = 2.f*a[6]-f.x; a[7] = 2.f*a[7]-f.y;
    }
    uint4 r;
    r.x = h2u(__floats2half2_rn(a[0], a[1]));
    r.y = h2u(__floats2half2_rn(a[2], a[3]));
    r.z = h2u(__floats2half2_rn(a[4], a[5]));
    r.w = h2u(__floats2half2_rn(a[6], a[7]));
    *(uint4*)(o + (long)v*BF_ + j0) = r;
}

// ---------------- FP16 tensor-core GEMM (m16n8k16, ldmatrix) -----------------
// A smem row-major [m][k] pitch 40 halves; B smem row-major [k][n] pitch 264.
// FIXED vs R16: full tile coverage.
//   A fill: 256 threads x 1 uint4: row = tid>>2 (0..63), seg = tid&3 -> 2048 halves.
//   B fill: 256 threads x 4 uint4: item = tid+i*256, k = item>>5 (0..31),
//           seg = item&31, offset seg*8 -> 8192 halves.
#define BM 64
#define BN 256
#define BK 32
#define NCH (KCH_ * FIN_ / BK)   // 32 chunks
#define APITCH 40
#define BPITCH 264
#define A_HALVES (64*APITCH)     // 2560 per buffer
#define B_HALVES (32*BPITCH)     // 8448 per buffer

__device__ __forceinline__ void ldsm_x4(uint32_t& r0, uint32_t& r1,
                                        uint32_t& r2, uint32_t& r3,
                                        const __half* p) {
    uint32_t a = (uint32_t)__cvta_generic_to_shared(p);
    asm volatile("ldmatrix.sync.aligned.m8n8.x4.shared.b16 {%0,%1,%2,%3}, [%4];"
                 : "=r"(r0), "=r"(r1), "=r"(r2), "=r"(r3) : "r"(a));
}
__device__ __forceinline__ void ldsm_x4t(uint32_t& r0, uint32_t& r1,
                                         uint32_t& r2, uint32_t& r3,
                                         const __half* p) {
    uint32_t a = (uint32_t)__cvta_generic_to_shared(p);
    asm volatile("ldmatrix.sync.aligned.m8n8.x4.trans.shared.b16 {%0,%1,%2,%3}, [%4];"
                 : "=r"(r0), "=r"(r1), "=r"(r2), "=r"(r3) : "r"(a));
}

__global__ __launch_bounds__(256) void k_gemm() {
    __shared__ __align__(16) __half smA[2*A_HALVES];   // 10240 B
    __shared__ __align__(16) __half smB[2*B_HALVES];   // 33792 B
    __shared__ float s_s[BN], s_q[BN];                 //  2048 B

    const int b     = blockIdx.y;
    const int vbase = blockIdx.x * BM;
    const int tid  = threadIdx.x;
    const int lane = tid & 31, warp = tid >> 5;
    const int wm = warp & 1, wn = warp >> 1;   // 2 warps along M, 4 along N

    s_s[tid] = 0.f; s_q[tid] = 0.f;

    float acc[2][8][4];
    #pragma unroll
    for (int i = 0; i < 2; ++i)
        #pragma unroll
        for (int j = 0; j < 8; ++j)
            #pragma unroll
            for (int c = 0; c < 4; ++c) acc[i][j][c] = 0.f;

    uint4 pa;          // A: 1 uint4 per thread
    uint4 pbv[4];      // B: 4 uint4 per thread

    const int a_row = tid >> 2, a_seg = tid & 3;

    auto prefetch = [&](int t) {
        const int p  = t >> 3;
        const int kb = (t & 7) * BK;
        const __half* ab; long as_;
        if (p == 0)      { ab = g_Xh  + (long)b*V_*FIN_; as_ = FIN_; }
        else if (p == 1) { ab = g_T1h + (long)b*FIN_;    as_ = BF_;  }
        else if (p == 2) { ab = g_T2h + (long)b*FIN_;    as_ = BF_;  }
        else             { ab = g_T3h + (long)b*FIN_;    as_ = BF_;  }
        pa = *(const uint4*)(ab + (long)(vbase + a_row)*as_ + kb + a_seg*8);
        const __half* wb = g_Wh + ((long)p*FIN_ + kb)*FOUT_;
        #pragma unroll
        for (int i = 0; i < 4; ++i) {
            int item = tid + i*256;
            int k = item >> 5, seg = item & 31;
            pbv[i] = *(const uint4*)(wb + (long)k*FOUT_ + seg*8);
        }
    };

    prefetch(0);
    int cur = 0;
    #pragma unroll 1
    for (int t = 0; t < NCH; ++t) {
        __half* Ac = smA + cur*A_HALVES;
        __half* Bc = smB + cur*B_HALVES;
        *(uint4*)(Ac + a_row*APITCH + a_seg*8) = pa;
        #pragma unroll
        for (int i = 0; i < 4; ++i) {
            int item = tid + i*256;
            int k = item >> 5, seg = item & 31;
            *(uint4*)(Bc + k*BPITCH + seg*8) = pbv[i];
        }
        __syncthreads();
        if (t + 1 < NCH) prefetch(t + 1);   // overlap global loads with mma

        #pragma unroll
        for (int kb2 = 0; kb2 < 2; ++kb2) {
            uint32_t a[2][4];
            #pragma unroll
            for (int mt = 0; mt < 2; ++mt) {
                int row = wm*32 + mt*16 + (lane & 15);
                int ko  = kb2*16 + (lane >> 4)*8;
                ldsm_x4(a[mt][0], a[mt][1], a[mt][2], a[mt][3],
                        Ac + row*APITCH + ko);
            }
            uint32_t bf[8][2];
            #pragma unroll
            for (int ng = 0; ng < 4; ++ng) {
                int krow = kb2*16 + (lane & 7) + ((lane >> 3) & 1)*8;
                int ncol = wn*64 + ng*16 + ((lane >> 4) & 1)*8;
                uint32_t r0, r1, r2, r3;
                ldsm_x4t(r0, r1, r2, r3, Bc + krow*BPITCH + ncol);
                bf[ng*2  ][0] = r0; bf[ng*2  ][1] = r1;
                bf[ng*2+1][0] = r2; bf[ng*2+1][1] = r3;
            }
            #pragma unroll
            for (int nt = 0; nt < 8; ++nt)
                #pragma unroll
                for (int mt = 0; mt < 2; ++mt) {
                    asm volatile(
                        "mma.sync.aligned.m16n8k16.row.col.f32.f16.f16.f32 "
                        "{%0,%1,%2,%3}, {%4,%5,%6,%7}, {%8,%9}, {%0,%1,%2,%3};\n"
                        : "+f"(acc[mt][nt][0]), "+f"(acc[mt][nt][1]),
                          "+f"(acc[mt][nt][2]), "+f"(acc[mt][nt][3])
                        : "r"(a[mt][0]), "r"(a[mt][1]),
                          "r"(a[mt][2]), "r"(a[mt][3]),
                          "r"(bf[nt][0]), "r"(bf[nt][1]));
                }
        }
        cur ^= 1;
    }

    const int g = lane >> 2, tg = lane & 3;

    // epilogue: write pre-BN result as fp16
    #pragma unroll
    for (int mt = 0; mt < 2; ++mt) {
        int row0 = vbase + wm*32 + mt*16 + g;
        #pragma unroll
        for (int nt = 0; nt < 8; ++nt) {
            int col = wn*64 + nt*8 + tg*2;
            uint32_t v0 = h2u(__floats2half2_rn(acc[mt][nt][0], acc[mt][nt][1]));
            uint32_t v1 = h2u(__floats2half2_rn(acc[mt][nt][2], acc[mt][nt][3]));
            *(uint32_t*)&g_Oh[((long)b*V_ + row0    )*FOUT_ + col] = v0;
            *(uint32_t*)&g_Oh[((long)b*V_ + row0 + 8)*FOUT_ + col] = v1;
        }
    }

    // fused BN stats: per-column sum / sumsq over this block's 64 rows (f32)
    #pragma unroll
    for (int nt = 0; nt < 8; ++nt) {
        float s0 = acc[0][nt][0] + acc[0][nt][2] + acc[1][nt][0] + acc[1][nt][2];
        float s1 = acc[0][nt][1] + acc[0][nt][3] + acc[1][nt][1] + acc[1][nt][3];
        float q0 = acc[0][nt][0]*acc[0][nt][0] + acc[0][nt][2]*acc[0][nt][2]
                 + acc[1][nt][0]*acc[1][nt][0] + acc[1][nt][2]*acc[1][nt][2];
        float q1 = acc[0][nt][1]*acc[0][nt][1] + acc[0][nt][3]*acc[0][nt][3]
                 + acc[1][nt][1]*acc[1][nt][1] + acc[1][nt][3]*acc[1][nt][3];
        #pragma unroll
        for (int m = 4; m <= 16; m <<= 1) {
            s0 += __shfl_xor_sync(0xffffffffu, s0, m);
            s1 += __shfl_xor_sync(0xffffffffu, s1, m);
            q0 += __shfl_xor_sync(0xffffffffu, q0, m);
            q1 += __shfl_xor_sync(0xffffffffu, q1, m);
        }
        if (lane < 4) {
            int colr = wn*64 + nt*8 + tg*2;
            atomicAdd(&s_s[colr  ], s0); atomicAdd(&s_q[colr  ], q0);
            atomicAdd(&s_s[colr+1], s1); atomicAdd(&s_q[colr+1], q1);
        }
    }
    __syncthreads();
    atomicAdd(&g_sum[tid], s_s[tid]);
    atomicAdd(&g_sq[tid],  s_q[tid]);
}

// ---------------- BatchNorm finalize + apply + ReLU -------------------------
__global__ void k_bnfinal(const float* __restrict__ gamma,
                          const float* __restrict__ beta) {
    int o = threadIdx.x;
    const float n = (float)ROWS_;
    float mean = g_sum[o] / n;
    float var  = g_sq[o] / n - mean*mean;      // biased variance (torch-style)
    float sc   = gamma[o] * rsqrtf(var + 1e-5f);
    g_scale[o] = sc;
    g_shift[o] = beta[o] - mean*sc;
    g_sum[o] = 0.f;
    g_sq[o]  = 0.f;
}

__global__ __launch_bounds__(256) void k_bnapply(float* __restrict__ out) {
    long i = ((long)blockIdx.x*blockDim.x + threadIdx.x) * 8;
    uint4 h = *(const uint4*)(g_Oh + i);
    float2 f0 = __half22float2(*(__half2*)&h.x);
    float2 f1 = __half22float2(*(__half2*)&h.y);
    float2 f2 = __half22float2(*(__half2*)&h.z);
    float2 f3 = __half22float2(*(__half2*)&h.w);
    int o = (int)(i & 255);
    float4 v0, v1;
    v0.x = fmaxf(fmaf(f0.x, g_scale[o  ], g_shift[o  ]), 0.f);
    v0.y = fmaxf(fmaf(f0.y, g_scale[o+1], g_shift[o+1]), 0.f);
    v0.z = fmaxf(fmaf(f1.x, g_scale[o+2], g_shift[o+2]), 0.f);
    v0.w = fmaxf(fmaf(f1.y, g_scale[o+3], g_shift[o+3]), 0.f);
    v1.x = fmaxf(fmaf(f2.x, g_scale[o+4], g_shift[o+4]), 0.f);
    v1.y = fmaxf(fmaf(f2.y, g_scale[o+5], g_shift[o+5]), 0.f);
    v1.z = fmaxf(fmaf(f3.x, g_scale[o+6], g_shift[o+6]), 0.f);
    v1.w = fmaxf(fmaf(f3.y, g_scale[o+7], g_shift[o+7]), 0.f);
    *(float4*)(out + i)     = v0;
    *(float4*)(out + i + 4) = v1;
}

// ---------------- launch -----------------------------------------------------
extern "C" void kernel_launch(void* const* d_in, const int* in_sizes, int n_in,
                              void* d_out, int out_size) {
    const float* x     = (const float*)d_in[0];
    const float* ew    = (const float*)d_in[1];
    const float* w     = (const float*)d_in[2];
    const float* bias  = (const float*)d_in[3]; (void)bias; // cancels under BN
    const float* gamma = (const float*)d_in[4];
    const float* beta  = (const float*)d_in[5];
    const int*   esrc  = (const int*)d_in[6];
    const int*   edst  = (const int*)d_in[7];
    float* out = (float*)d_out;
    (void)in_sizes; (void)n_in; (void)out_size;

    // fp16 conversions (k_xh also zeroes g_cnt ahead of k_hist)
    k_xh<<<(B_*V_*FIN_)/(256*8), 256>>>(x);
    k_wh<<<KCH_*FIN_, 128>>>(w);

    // CSR build
    k_hist<<<E_/256, 256>>>(edst);
    k_scan<<<1, 1024>>>();
    k_scatter<<<E_/256, 256>>>(esrc, edst, ew);

    // Chebyshev recursion (fp16, full-row blocks, uint4 gathers)
    k_spmm<<<V_, 256>>>(1);
    k_spmm<<<V_, 256>>>(2);
    k_spmm<<<V_, 256>>>(3);

    // FP16 tensor-core GEMM (ldmatrix) -> fp16 pre-BN output + BN statistics
    dim3 gg(V_/BM, B_);
    k_gemm<<<gg, 256>>>();

    // BatchNorm finalize + apply + ReLU (fp16 in, f32 out)
    k_bnfinal<<<1, FOUT_>>>(gamma, beta);
    k_bnapply<<<(ROWS_*FOUT_)/8/256, 256>>>(out);
}